// round 9
// baseline (speedup 1.0000x reference)
#include <cuda_runtime.h>
#include <stdint.h>
#include <math.h>

#define NN   8192
#define WPR  256          // 8192 bits / 32 per word
#define MAXE 262144

// ---------------- device scratch (static, no allocation) ----------------
static __device__ uint32_t g_adj0[NN * WPR];   // dedup bitmask (8 MB)
static __device__ int      g_rowptr[NN + 1];
static __device__ int      g_cols[MAXE];
static __device__ int      g_rows[MAXE];
static __device__ uint8_t  g_flagsA[MAXE];
static __device__ uint8_t  g_flagsB[MAXE];
static __device__ int      g_deg0[NN];
static __device__ int      g_degA[NN];
static __device__ int      g_degB[NN];
static __device__ float    g_za[NN * 64];
static __device__ float    g_zb[NN * 64];
static __device__ float    g_gt[NN * 64];
static __device__ int      g_is64;

// ---------------- Threefry-2x32 (exact JAX constants/rounds) ----------------
__host__ __device__ __forceinline__ void tf2x32(uint32_t k0, uint32_t k1,
                                                uint32_t &x0, uint32_t &x1) {
  uint32_t k2 = k0 ^ k1 ^ 0x1BD11BDAu;
  x0 += k0; x1 += k1;
#define TF_RND(r) { x0 += x1; x1 = (x1 << (r)) | (x1 >> (32 - (r))); x1 ^= x0; }
  TF_RND(13) TF_RND(15) TF_RND(26) TF_RND(6)
  x0 += k1; x1 += k2 + 1u;
  TF_RND(17) TF_RND(29) TF_RND(16) TF_RND(24)
  x0 += k2; x1 += k0 + 2u;
  TF_RND(13) TF_RND(15) TF_RND(26) TF_RND(6)
  x0 += k0; x1 += k1 + 3u;
  TF_RND(17) TF_RND(29) TF_RND(16) TF_RND(24)
  x0 += k1; x1 += k2 + 4u;
  TF_RND(13) TF_RND(15) TF_RND(26) TF_RND(6)
  x0 += k2; x1 += k0 + 5u;
#undef TF_RND
}

// partitionable threefry: element n -> counter (0, n); bits = out0 ^ out1
__device__ __forceinline__ float jax_uniform01(uint32_t k0, uint32_t k1, uint32_t n) {
  uint32_t x0 = 0u, x1 = n;
  tf2x32(k0, k1, x0, x1);
  uint32_t bits = x0 ^ x1;
  return __uint_as_float((bits >> 9) | 0x3f800000u) - 1.0f;
}

// ---------------- setup kernels ----------------
__global__ void k_clear(uint32_t *p) {
  p[blockIdx.x * blockDim.x + threadIdx.x] = 0u;
}

__global__ void k_detect(const void *ev) {
  const unsigned long long *p = (const unsigned long long *)ev;
  int lane = threadIdx.x;
  bool big = false;
  for (int k = lane; k < 512; k += 32) big |= (p[k] > 8191ull);
  unsigned m = __ballot_sync(0xffffffffu, big);
  if (lane == 0) g_is64 = (m == 0u);
}

// scatter bits (dedup) + zero the two per-layer degree arrays
__global__ void k_scatter(uint32_t *adj0, const void *ev, int n,
                          int *degA, int *degB) {
  int k = blockIdx.x * blockDim.x + threadIdx.x;
  if (k < NN) { degA[k] = 0; degB[k] = 0; }
  if (k >= n) return;
  int r, c;
  if (g_is64) {
    const long long *e = (const long long *)ev;
    r = (int)e[k]; c = (int)e[k + n];
  } else {
    const int *e = (const int *)ev;
    r = e[k]; c = e[k + n];
  }
  atomicOr(&adj0[r * WPR + (c >> 5)], 1u << (c & 31));
}

// one warp per row: degree via popcount
__global__ void k_count(const uint32_t *__restrict__ adj, int *__restrict__ deg) {
  int row = (blockIdx.x * blockDim.x + threadIdx.x) >> 5;
  int lane = threadIdx.x & 31;
  const uint4 *r = (const uint4 *)(adj + row * WPR);
  int s = 0;
#pragma unroll
  for (int kk = 0; kk < 2; kk++) {
    uint4 v = r[lane + kk * 32];
    s += __popc(v.x) + __popc(v.y) + __popc(v.z) + __popc(v.w);
  }
#pragma unroll
  for (int d = 16; d; d >>= 1) s += __shfl_down_sync(0xffffffffu, s, d);
  if (lane == 0) deg[row] = s;
}

// exclusive prefix of 8192 degrees -> rowptr[0..8192]; 1 block, 1024 threads x 8
__global__ void k_scan(const int *__restrict__ deg, int *__restrict__ rowptr) {
  __shared__ int wsum[32];
  int t = threadIdx.x;
  int base = t * 8;
  int v[8], s = 0;
#pragma unroll
  for (int k = 0; k < 8; k++) { v[k] = deg[base + k]; s += v[k]; }
  int lane = t & 31, wid = t >> 5;
  int inc = s;
#pragma unroll
  for (int d = 1; d < 32; d <<= 1) {
    int n = __shfl_up_sync(0xffffffffu, inc, d);
    if (lane >= d) inc += n;
  }
  if (lane == 31) wsum[wid] = inc;
  __syncthreads();
  if (wid == 0) {
    int w = wsum[lane];
#pragma unroll
    for (int d = 1; d < 32; d <<= 1) {
      int n = __shfl_up_sync(0xffffffffu, w, d);
      if (lane >= d) w += n;
    }
    wsum[lane] = w;                    // inclusive warp sums
  }
  __syncthreads();
  int run = inc - s + (wid ? wsum[wid - 1] : 0);
#pragma unroll
  for (int k = 0; k < 8; k++) { rowptr[base + k] = run; run += v[k]; }
  if (t == 1023) rowptr[NN] = run;
}

// one warp per row: emit cols (ascending j -> deterministic) + rows
__global__ void k_fill(const uint32_t *__restrict__ adj, const int *__restrict__ rowptr,
                       int *__restrict__ rows, int *__restrict__ cols) {
  int row = (blockIdx.x * blockDim.x + threadIdx.x) >> 5;
  int lane = threadIdx.x & 31;
  uint32_t wv[8];
  int cnt = 0;
#pragma unroll
  for (int k = 0; k < 8; k++) {
    wv[k] = adj[row * WPR + lane * 8 + k];
    cnt += __popc(wv[k]);
  }
  int v = cnt;
#pragma unroll
  for (int d = 1; d < 32; d <<= 1) {
    int n = __shfl_up_sync(0xffffffffu, v, d);
    if (lane >= d) v += n;
  }
  int p = rowptr[row] + v - cnt;       // exclusive offset
#pragma unroll
  for (int k = 0; k < 8; k++) {
    uint32_t m = wv[k];
    while (m) {
      int bit = __ffs(m) - 1; m &= m - 1;
      cols[p] = ((lane * 8 + k) << 5) + bit;
      rows[p] = row;
      p++;
    }
  }
}

// ---------------- compute kernels ----------------
// g = rsqrt(deg+1) * (zin @ W); 128 threads, 16 rows/block
template <int KIN, int C>
__global__ void k_gemm_tiled(const float *__restrict__ zin, const float *__restrict__ W,
                             const int *__restrict__ deg, float *__restrict__ gt) {
  const int NC = C / 32;
  __shared__ float Ws[KIN * C];
  __shared__ float Zs[16 * KIN];
  int t = threadIdx.x;
  int row0 = blockIdx.x * 16;
  for (int i = t; i < KIN * C / 4; i += 128)
    ((float4 *)Ws)[i] = ((const float4 *)W)[i];
  for (int i = t; i < 16 * KIN / 4; i += 128)
    ((float4 *)Zs)[i] = ((const float4 *)(zin + row0 * KIN))[i];
  __syncthreads();

  int warp = t >> 5, lane = t & 31;
  float acc[4][NC];
#pragma unroll
  for (int r = 0; r < 4; r++)
#pragma unroll
    for (int c = 0; c < NC; c++) acc[r][c] = 0.f;

#pragma unroll 4
  for (int k = 0; k < KIN; k++) {
    float wv[NC];
#pragma unroll
    for (int c = 0; c < NC; c++) wv[c] = Ws[k * C + lane + c * 32];
#pragma unroll
    for (int r = 0; r < 4; r++) {
      float zv = Zs[(warp * 4 + r) * KIN + k];
#pragma unroll
      for (int c = 0; c < NC; c++) acc[r][c] += zv * wv[c];
    }
  }
#pragma unroll
  for (int r = 0; r < 4; r++) {
    int row = row0 + warp * 4 + r;
    float dv = rsqrtf((float)deg[row] + 1.0f);
#pragma unroll
    for (int c = 0; c < NC; c++) gt[row * C + lane + c * 32] = dv * acc[r][c];
  }
}

// z_i = dropout(relu(dv_i*(g_i + sum_{kept j} g_j) + b)); CSR row loop, no syncs
template <int C, bool F>
__global__ void k_aggregate_csr(const int *__restrict__ rowptr, const int *__restrict__ cols,
                                const uint8_t *__restrict__ flags,
                                const float *__restrict__ gt, const int *__restrict__ deg,
                                const float *__restrict__ b, float *__restrict__ zout,
                                uint32_t kd0, uint32_t kd1) {
  const int RPB = 256 / C;             // rows per block
  int rloc = threadIdx.x / C;
  int c = threadIdx.x % C;
  int i = blockIdx.x * RPB + rloc;
  int base = rowptr[i];
  int ne = rowptr[i + 1] - base;
  float dv = rsqrtf((float)deg[i] + 1.0f);

  float a0 = gt[i * C + c], a1 = 0.f, a2 = 0.f, a3 = 0.f;
  int e = 0;
  for (; e + 4 <= ne; e += 4) {
    int c0 = cols[base + e],     c1 = cols[base + e + 1];
    int c2 = cols[base + e + 2], c3 = cols[base + e + 3];
    if (!F || flags[base + e])     a0 += gt[c0 * C + c];
    if (!F || flags[base + e + 1]) a1 += gt[c1 * C + c];
    if (!F || flags[base + e + 2]) a2 += gt[c2 * C + c];
    if (!F || flags[base + e + 3]) a3 += gt[c3 * C + c];
  }
  for (; e < ne; e++)
    if (!F || flags[base + e]) a0 += gt[cols[base + e] * C + c];
  float acc = (a0 + a1) + (a2 + a3);

  float val = dv * acc + b[c];
  val = fmaxf(val, 0.0f);
  float u = jax_uniform01(kd0, kd1, (uint32_t)(i * C + c));
  zout[i * C + c] = (u < 0.9f) ? (val / 0.9f) : 0.0f;
}

// edge-centric resample: keep[e] = uniform < sigmoid(z_i . z_j); deg[i] += keep.
// 256 threads = 32 edges/block x 8 lanes; all lanes always execute (shfl-safe).
__global__ void k_resample_e(const int *__restrict__ rows, const int *__restrict__ cols,
                             const int *__restrict__ rowptr, const float *__restrict__ z,
                             uint8_t *__restrict__ flags, int *__restrict__ deg,
                             uint32_t kb0, uint32_t kb1) {
  int t = threadIdx.x;
  int eg = blockIdx.x * 32 + (t >> 3);
  int s = t & 7;
  int nE = rowptr[NN];
  bool active = (eg < nE);
  int i = active ? rows[eg] : 0;
  int j = active ? cols[eg] : 0;
  const float4 *zi = (const float4 *)(z + i * 64);
  const float4 *zj = (const float4 *)(z + j * 64);
  float4 a0 = zi[s],     b0 = zj[s];
  float4 a1 = zi[s + 8], b1 = zj[s + 8];
  float d = a0.x * b0.x + a0.y * b0.y + a0.z * b0.z + a0.w * b0.w
          + a1.x * b1.x + a1.y * b1.y + a1.z * b1.z + a1.w * b1.w;
#pragma unroll
  for (int o = 4; o; o >>= 1) d += __shfl_down_sync(0xffffffffu, d, o, 8);
  if (active && s == 0) {
    float p = 1.0f / (1.0f + expf(-d));
    float u = jax_uniform01(kb0, kb1, (uint32_t)i * (uint32_t)NN + (uint32_t)j);
    uint8_t f = (u < p) ? 1 : 0;
    flags[eg] = f;
    if (f) atomicAdd(&deg[i], 1);
  }
}

// ---------------- launch ----------------
extern "C" void kernel_launch(void *const *d_in, const int *in_sizes, int n_in,
                              void *d_out, int out_size) {
  const float *x  = (const float *)d_in[0];
  const float *W0 = (const float *)d_in[1];
  const float *b0 = (const float *)d_in[2];
  const float *W1 = (const float *)d_in[3];
  const float *b1 = (const float *)d_in[4];
  const float *W2 = (const float *)d_in[5];
  const float *b2 = (const float *)d_in[6];
  const void  *ei = (const void  *)d_in[7];
  int nE = in_sizes[7] / 2;

  // JAX key schedule (partitionable threefry):
  // r_i = block((0,42),(0,i)); kd = block(r_i,(0,0)); kb = block(r_i,(0,1))
  uint32_t kd[3][2], kb[3][2];
  for (int i = 0; i < 3; i++) {
    uint32_t f0 = 0u, f1 = (uint32_t)i;
    tf2x32(0u, 42u, f0, f1);
    uint32_t a0 = 0u, a1 = 0u; tf2x32(f0, f1, a0, a1);
    uint32_t c0 = 0u, c1 = 1u; tf2x32(f0, f1, c0, c1);
    kd[i][0] = a0; kd[i][1] = a1;
    kb[i][0] = c0; kb[i][1] = c1;
  }

  uint32_t *adj0; int *rowptr, *cols, *rows, *deg0, *degA, *degB;
  uint8_t *flA, *flB; float *za, *zb, *gt;
  cudaGetSymbolAddress((void **)&adj0,   g_adj0);
  cudaGetSymbolAddress((void **)&rowptr, g_rowptr);
  cudaGetSymbolAddress((void **)&cols,   g_cols);
  cudaGetSymbolAddress((void **)&rows,   g_rows);
  cudaGetSymbolAddress((void **)&deg0,   g_deg0);
  cudaGetSymbolAddress((void **)&degA,   g_degA);
  cudaGetSymbolAddress((void **)&degB,   g_degB);
  cudaGetSymbolAddress((void **)&flA,    g_flagsA);
  cudaGetSymbolAddress((void **)&flB,    g_flagsB);
  cudaGetSymbolAddress((void **)&za,     g_za);
  cudaGetSymbolAddress((void **)&zb,     g_zb);
  cudaGetSymbolAddress((void **)&gt,     g_gt);

  // ---- build CSR (dedup via bitmask) ----
  k_clear<<<(NN * WPR) / 1024, 1024>>>(adj0);
  k_detect<<<1, 32>>>(ei);
  k_scatter<<<(nE + 255) / 256, 256>>>(adj0, ei, nE, degA, degB);
  k_count<<<NN / 8, 256>>>(adj0, deg0);
  k_scan<<<1, 1024>>>(deg0, rowptr);
  k_fill<<<NN / 8, 256>>>(adj0, rowptr, rows, cols);

  // ---- layer 0 (original adjacency) ----
  k_gemm_tiled<128, 64><<<NN / 16, 128>>>(x, W0, deg0, gt);
  k_aggregate_csr<64, false><<<NN / 4, 256>>>(rowptr, cols, flA, gt, deg0, b0, za,
                                              kd[0][0], kd[0][1]);
  k_resample_e<<<MAXE / 32, 256>>>(rows, cols, rowptr, za, flA, degA,
                                   kb[0][0], kb[0][1]);

  // ---- layer 1 ----
  k_gemm_tiled<64, 64><<<NN / 16, 128>>>(za, W1, degA, gt);
  k_aggregate_csr<64, true><<<NN / 4, 256>>>(rowptr, cols, flA, gt, degA, b1, zb,
                                             kd[1][0], kd[1][1]);
  k_resample_e<<<MAXE / 32, 256>>>(rows, cols, rowptr, zb, flB, degB,
                                   kb[1][0], kb[1][1]);

  // ---- layer 2 (output straight to d_out) ----
  k_gemm_tiled<64, 32><<<NN / 16, 128>>>(zb, W2, degB, gt);
  k_aggregate_csr<32, true><<<NN / 8, 256>>>(rowptr, cols, flB, gt, degB, b2,
                                             (float *)d_out, kd[2][0], kd[2][1]);
}